// round 1
// baseline (speedup 1.0000x reference)
#include <cuda_runtime.h>
#include <math.h>

#define L 512
#define LL (L*L)
#define ZD 128
#define CD 128

// ---- scratch (device globals; allocation-free contract) ----
__device__ float g_zn[(size_t)LL*ZD];   // LN(z)                 [row][k]
__device__ float g_P [(size_t)LL*CD];   // zn @ a_w^T + a_b      [row][c]
__device__ float g_Q [(size_t)LL*CD];   // sigmoid(zn@ag_w^T+b)  [row][c]
__device__ float g_gate[(size_t)LL*ZD]; // sigmoid(zn@g_w^T+b)   [row][z]
__device__ float g_at[(size_t)CD*LL];   // a transposed          [c][i*512+l]
__device__ float g_o [(size_t)CD*LL];   // einsum output         [c][i*512+j]
__device__ float g_o2[(size_t)LL*CD];   // LN(o) re-transposed   [row][c]

__device__ __forceinline__ float sigmoidf_(float x) { return 1.0f / (1.0f + expf(-x)); }

// ============================================================
// K1: LayerNorm of z rows (128 elems each). 1 warp per row.
// ============================================================
__global__ void ln_kernel(const float* __restrict__ z,
                          const float* __restrict__ gam,
                          const float* __restrict__ bet) {
    int row  = blockIdx.x * 8 + (threadIdx.x >> 5);
    int lane = threadIdx.x & 31;
    float4 v = reinterpret_cast<const float4*>(z)[(size_t)row * 32 + lane];
    float s = v.x + v.y + v.z + v.w;
    float q = v.x*v.x + v.y*v.y + v.z*v.z + v.w*v.w;
#pragma unroll
    for (int o = 16; o > 0; o >>= 1) {
        s += __shfl_xor_sync(0xffffffffu, s, o);
        q += __shfl_xor_sync(0xffffffffu, q, o);
    }
    float mean = s * (1.0f / 128.0f);
    float var  = q * (1.0f / 128.0f) - mean * mean;
    float rs   = rsqrtf(var + 1e-5f);
    float4 g4 = reinterpret_cast<const float4*>(gam)[lane];
    float4 b4 = reinterpret_cast<const float4*>(bet)[lane];
    float4 o4;
    o4.x = (v.x - mean) * rs * g4.x + b4.x;
    o4.y = (v.y - mean) * rs * g4.y + b4.y;
    o4.z = (v.z - mean) * rs * g4.z + b4.z;
    o4.w = (v.w - mean) * rs * g4.w + b4.w;
    reinterpret_cast<float4*>(g_zn)[(size_t)row * 32 + lane] = o4;
}

// ============================================================
// K2: projection GEMM: out[m][n] = f( sum_k X[m][k]*W[n][k] + bias[n] )
//     M-tile 128, N = 128 (full), K = 128. 256 thr, 8x8 micro.
// MODE: 0 plain, 1 sigmoid, 2 multiply-by-gate (final output)
// ============================================================
template<int MODE>
__global__ void __launch_bounds__(256, 2)
proj_kernel(const float* __restrict__ X,
            const float* __restrict__ W,
            const float* __restrict__ bias,
            float* __restrict__ out) {
    __shared__ float Xs[8][132];
    __shared__ float Ws[8][132];
    const int tid = threadIdx.x;
    const int ty = tid >> 4, tx = tid & 15;
    const size_t m0 = (size_t)blockIdx.x * 128;

    float acc[8][8];
#pragma unroll
    for (int r = 0; r < 8; r++)
#pragma unroll
        for (int s2 = 0; s2 < 8; s2++) acc[r][s2] = 0.0f;

    for (int k0 = 0; k0 < 128; k0 += 8) {
#pragma unroll
        for (int e = 0; e < 4; e++) {
            int li = tid + 256 * e;
            int r = li >> 3, kk = li & 7;
            Xs[kk][r] = X[(m0 + r) * 128 + (k0 + kk)];
            Ws[kk][r] = W[r * 128 + (k0 + kk)];
        }
        __syncthreads();
#pragma unroll
        for (int kk = 0; kk < 8; kk++) {
            float4 a0 = *reinterpret_cast<const float4*>(&Xs[kk][ty * 8]);
            float4 a1 = *reinterpret_cast<const float4*>(&Xs[kk][ty * 8 + 4]);
            float4 b0 = *reinterpret_cast<const float4*>(&Ws[kk][tx * 8]);
            float4 b1 = *reinterpret_cast<const float4*>(&Ws[kk][tx * 8 + 4]);
            float ra[8] = {a0.x, a0.y, a0.z, a0.w, a1.x, a1.y, a1.z, a1.w};
            float rb[8] = {b0.x, b0.y, b0.z, b0.w, b1.x, b1.y, b1.z, b1.w};
#pragma unroll
            for (int r = 0; r < 8; r++)
#pragma unroll
                for (int s2 = 0; s2 < 8; s2++)
                    acc[r][s2] += ra[r] * rb[s2];
        }
        __syncthreads();
    }

#pragma unroll
    for (int r = 0; r < 8; r++) {
        size_t row = m0 + (size_t)(ty * 8 + r);
#pragma unroll
        for (int s2 = 0; s2 < 8; s2++) {
            int n = tx * 8 + s2;
            float v = acc[r][s2] + bias[n];
            if (MODE == 1) v = sigmoidf_(v);
            if (MODE == 2) v *= g_gate[row * 128 + n];
            out[row * 128 + n] = v;
        }
    }
}

// ============================================================
// K3: a = P * Q (Q already sigmoided), transposed to [c][row].
//     64 rows x 128 c per block via smem.
// ============================================================
__global__ void act_transpose_kernel() {
    __shared__ float S[64][132];
    const size_t row0 = (size_t)blockIdx.x * 64;
    for (int idx = threadIdx.x; idx < 64 * 128; idx += 256) {
        int r = idx >> 7, c = idx & 127;
        float p = g_P[(row0 + r) * 128 + c];
        float q = g_Q[(row0 + r) * 128 + c];
        S[r][c] = p * q;
    }
    __syncthreads();
    for (int idx = threadIdx.x; idx < 64 * 128; idx += 256) {
        int c = idx >> 6, r = idx & 63;
        g_at[(size_t)c * LL + row0 + r] = S[r][c];
    }
}

// ============================================================
// K4: per-channel SYRK: O_c = A_c * A_c^T, A_c = a_t[c] (512x512).
//     128x128 tiles, upper triangle only (10 tile pairs), mirror
//     written via smem transpose staging.
// ============================================================
__global__ void __launch_bounds__(256, 2)
syrk_kernel() {
    __shared__ float smem[4224];         // sA[16][132] + sB[16][132]; reused as T[32][132]
    float* sA = smem;
    float* sB = smem + 16 * 132;

    const int c = blockIdx.y;
    int p = blockIdx.x;
    int bi = 0, rem = p, span = 4;
    while (rem >= span) { rem -= span; span--; bi++; }
    int bj = bi + rem;
    const int i0 = bi * 128, j0 = bj * 128;

    const float* __restrict__ A = g_at + (size_t)c * LL;
    float* __restrict__ O = g_o + (size_t)c * LL;

    const int tid = threadIdx.x;
    const int ty = tid >> 4, tx = tid & 15;

    float acc[8][8];
#pragma unroll
    for (int r = 0; r < 8; r++)
#pragma unroll
        for (int s2 = 0; s2 < 8; s2++) acc[r][s2] = 0.0f;

    for (int k0 = 0; k0 < 512; k0 += 16) {
#pragma unroll
        for (int e = 0; e < 8; e++) {
            int li = tid + 256 * e;
            int r = li >> 4, kk = li & 15;
            sA[kk * 132 + r] = A[(size_t)(i0 + r) * 512 + k0 + kk];
            sB[kk * 132 + r] = A[(size_t)(j0 + r) * 512 + k0 + kk];
        }
        __syncthreads();
#pragma unroll
        for (int kk = 0; kk < 16; kk++) {
            float4 a0 = *reinterpret_cast<const float4*>(&sA[kk * 132 + ty * 8]);
            float4 a1 = *reinterpret_cast<const float4*>(&sA[kk * 132 + ty * 8 + 4]);
            float4 b0 = *reinterpret_cast<const float4*>(&sB[kk * 132 + tx * 8]);
            float4 b1 = *reinterpret_cast<const float4*>(&sB[kk * 132 + tx * 8 + 4]);
            float ra[8] = {a0.x, a0.y, a0.z, a0.w, a1.x, a1.y, a1.z, a1.w};
            float rb[8] = {b0.x, b0.y, b0.z, b0.w, b1.x, b1.y, b1.z, b1.w};
#pragma unroll
            for (int r = 0; r < 8; r++)
#pragma unroll
                for (int s2 = 0; s2 < 8; s2++)
                    acc[r][s2] += ra[r] * rb[s2];
        }
        __syncthreads();
    }

    // direct tile write O[i0+m][j0+n]
#pragma unroll
    for (int r = 0; r < 8; r++) {
        size_t orow = (size_t)(i0 + ty * 8 + r) * 512 + j0;
#pragma unroll
        for (int s2 = 0; s2 < 8; s2++)
            O[orow + tx * 8 + s2] = acc[r][s2];
    }

    // mirror: O[j0+n][i0+m] via smem transpose, 32-row slices
    if (bi != bj) {
        for (int sblk = 0; sblk < 4; sblk++) {
            __syncthreads();
            if ((ty >> 2) == sblk) {
                int rb_ = (ty & 3) * 8;
#pragma unroll
                for (int r = 0; r < 8; r++)
#pragma unroll
                    for (int s2 = 0; s2 < 8; s2++)
                        smem[(rb_ + r) * 132 + tx * 8 + s2] = acc[r][s2];
            }
            __syncthreads();
            for (int idx = tid; idx < 128 * 32; idx += 256) {
                int nn = idx >> 5, rl = idx & 31;
                O[(size_t)(j0 + nn) * 512 + i0 + sblk * 32 + rl] = smem[rl * 132 + nn];
            }
        }
    }
}

// ============================================================
// K5: transpose o[c][i][j] -> o2[(i,j)][c], fused with LN over c.
//     block: fixed i, 64 j columns.
// ============================================================
__global__ void trans_ln_kernel(const float* __restrict__ og,
                                const float* __restrict__ ob) {
    __shared__ float S[128][65];
    __shared__ float ps[4][64], pq[4][64];
    __shared__ float mS[64], rS[64];
    const int i  = blockIdx.y;
    const int j0 = blockIdx.x * 64;
    const int tid = threadIdx.x;

    for (int idx = tid; idx < 128 * 64; idx += 256) {
        int c = idx >> 6, jj = idx & 63;
        S[c][jj] = g_o[(size_t)c * LL + (size_t)i * 512 + j0 + jj];
    }
    __syncthreads();

    int col = tid & 63, grp = tid >> 6;
    float s = 0.0f, q = 0.0f;
    for (int c = grp; c < 128; c += 4) { float v = S[c][col]; s += v; q += v * v; }
    ps[grp][col] = s; pq[grp][col] = q;
    __syncthreads();
    if (tid < 64) {
        float ss = 0.0f, qq = 0.0f;
#pragma unroll
        for (int g2 = 0; g2 < 4; g2++) { ss += ps[g2][tid]; qq += pq[g2][tid]; }
        float mean = ss * (1.0f / 128.0f);
        float var  = qq * (1.0f / 128.0f) - mean * mean;
        mS[tid] = mean;
        rS[tid] = rsqrtf(var + 1e-5f);
    }
    __syncthreads();

    for (int idx = tid; idx < 128 * 64; idx += 256) {
        int jj = idx >> 7, c = idx & 127;
        float v = (S[c][jj] - mS[jj]) * rS[jj] * og[c] + ob[c];
        g_o2[((size_t)i * 512 + j0 + jj) * 128 + c] = v;
    }
}

// ============================================================
// launch
// ============================================================
extern "C" void kernel_launch(void* const* d_in, const int* in_sizes, int n_in,
                              void* d_out, int out_size) {
    const float* z      = (const float*)d_in[0];
    const float* norm_g = (const float*)d_in[1];
    const float* norm_b = (const float*)d_in[2];
    const float* a_w    = (const float*)d_in[3];
    const float* a_b    = (const float*)d_in[4];
    const float* ag_w   = (const float*)d_in[5];
    const float* ag_b   = (const float*)d_in[6];
    const float* onorm_g= (const float*)d_in[7];
    const float* onorm_b= (const float*)d_in[8];
    const float* o_w    = (const float*)d_in[9];
    const float* o_b    = (const float*)d_in[10];
    const float* g_w    = (const float*)d_in[11];
    const float* g_b    = (const float*)d_in[12];
    float* out = (float*)d_out;

    float *zn, *P, *Q, *gate, *o2;
    cudaGetSymbolAddress((void**)&zn,   g_zn);
    cudaGetSymbolAddress((void**)&P,    g_P);
    cudaGetSymbolAddress((void**)&Q,    g_Q);
    cudaGetSymbolAddress((void**)&gate, g_gate);
    cudaGetSymbolAddress((void**)&o2,   g_o2);

    ln_kernel<<<LL / 8, 256>>>(z, norm_g, norm_b);

    proj_kernel<0><<<LL / 128, 256>>>(zn, a_w,  a_b,  P);
    proj_kernel<1><<<LL / 128, 256>>>(zn, ag_w, ag_b, Q);
    proj_kernel<1><<<LL / 128, 256>>>(zn, g_w,  g_b,  gate);

    act_transpose_kernel<<<LL / 64, 256>>>();

    syrk_kernel<<<dim3(10, 128), 256>>>();

    trans_ln_kernel<<<dim3(8, L), 256>>>(onorm_g, onorm_b);

    proj_kernel<2><<<LL / 128, 256>>>(o2, o_w, o_b, out);
}

// round 2
// speedup vs baseline: 2.4583x; 2.4583x over previous
#include <cuda_runtime.h>
#include <math.h>
#include <stdint.h>

#define L 512
#define LL (L*L)

// ---- scratch (device globals; allocation-free contract) ----
__device__ float g_zn[(size_t)LL*128];   // LN(z)
__device__ float g_P [(size_t)LL*128];   // (zn@a_w^T+a_b) * sigmoid(zn@ag_w^T+ag_b)
__device__ float g_Q [(size_t)LL*128];   // sigmoid(zn@ag_w^T+ag_b)
__device__ float g_gate[(size_t)LL*128]; // sigmoid(zn@g_w^T+g_b)
__device__ float g_at[(size_t)128*LL];   // a transposed [c][i*512+l]
__device__ float g_o [(size_t)128*LL];   // einsum output [c][i*512+j]
__device__ float g_o2[(size_t)LL*128];   // LN(o) re-transposed [row][c]

__device__ __forceinline__ float sigmoidf_(float x) { return 1.0f / (1.0f + expf(-x)); }

__device__ __forceinline__ uint32_t f2tf(float f) {
    uint32_t u;
    asm("cvt.rna.tf32.f32 %0, %1;" : "=r"(u) : "f"(f));
    return u;
}

__device__ __forceinline__ void mma8(float* c, const uint32_t* a, uint32_t b0, uint32_t b1) {
    asm volatile(
        "mma.sync.aligned.m16n8k8.row.col.f32.tf32.tf32.f32 "
        "{%0,%1,%2,%3}, {%4,%5,%6,%7}, {%8,%9}, {%0,%1,%2,%3};\n"
        : "+f"(c[0]), "+f"(c[1]), "+f"(c[2]), "+f"(c[3])
        : "r"(a[0]), "r"(a[1]), "r"(a[2]), "r"(a[3]), "r"(b0), "r"(b1));
}

// ============================================================
// K1: LayerNorm of z rows (128 elems). 1 warp per row.
// ============================================================
__global__ void ln_kernel(const float* __restrict__ z,
                          const float* __restrict__ gam,
                          const float* __restrict__ bet) {
    int row  = blockIdx.x * 8 + (threadIdx.x >> 5);
    int lane = threadIdx.x & 31;
    float4 v = reinterpret_cast<const float4*>(z)[(size_t)row * 32 + lane];
    float s = v.x + v.y + v.z + v.w;
    float q = v.x*v.x + v.y*v.y + v.z*v.z + v.w*v.w;
#pragma unroll
    for (int o = 16; o > 0; o >>= 1) {
        s += __shfl_xor_sync(0xffffffffu, s, o);
        q += __shfl_xor_sync(0xffffffffu, q, o);
    }
    float mean = s * (1.0f / 128.0f);
    float var  = q * (1.0f / 128.0f) - mean * mean;
    float rs   = rsqrtf(var + 1e-5f);
    float4 g4 = reinterpret_cast<const float4*>(gam)[lane];
    float4 b4 = reinterpret_cast<const float4*>(bet)[lane];
    float4 o4;
    o4.x = (v.x - mean) * rs * g4.x + b4.x;
    o4.y = (v.y - mean) * rs * g4.y + b4.y;
    o4.z = (v.z - mean) * rs * g4.z + b4.z;
    o4.w = (v.w - mean) * rs * g4.w + b4.w;
    reinterpret_cast<float4*>(g_zn)[(size_t)row * 32 + lane] = o4;
}

// ============================================================
// K2: tf32 tensor-core projection GEMM.
//     out[m][n] = f( sum_k X[m][k]*W[n][k] + bias[n] )
//     M-tile 128, N=128, K=128. 256 thr = 8 warps (4m x 2n),
//     warp tile 32x64, mma m16n8k8.
// MODE: 1 sigmoid, 2 *g_gate, 3 *g_Q
// ============================================================
template<int MODE>
__global__ void __launch_bounds__(256, 2)
proj_mma(const float* __restrict__ X, const float* __restrict__ W,
         const float* __restrict__ bias, float* __restrict__ out) {
    __shared__ uint32_t sX[128 * 36];
    __shared__ uint32_t sW[128 * 36];
    const int tid  = threadIdx.x;
    const int wid  = tid >> 5, lane = tid & 31;
    const int wm   = wid >> 1, wn = wid & 1;
    const int lr   = lane >> 2, lc = lane & 3;
    const size_t m0 = (size_t)blockIdx.x * 128;

    float acc[2][8][4];
#pragma unroll
    for (int mf = 0; mf < 2; mf++)
#pragma unroll
        for (int nf = 0; nf < 8; nf++)
#pragma unroll
            for (int v = 0; v < 4; v++) acc[mf][nf][v] = 0.0f;

    const float4* X4 = reinterpret_cast<const float4*>(X);
    const float4* W4 = reinterpret_cast<const float4*>(W);

    for (int kc4 = 0; kc4 < 32; kc4 += 8) {   // k chunk of 32 (8 float4s)
#pragma unroll
        for (int e = 0; e < 4; e++) {
            int idx = tid + 256 * e;
            int r = idx >> 3, c4 = idx & 7;
            float4 xv = X4[(m0 + r) * 32 + kc4 + c4];
            *reinterpret_cast<uint4*>(sX + r * 36 + c4 * 4) =
                make_uint4(f2tf(xv.x), f2tf(xv.y), f2tf(xv.z), f2tf(xv.w));
            float4 wv = W4[(size_t)r * 32 + kc4 + c4];
            *reinterpret_cast<uint4*>(sW + r * 36 + c4 * 4) =
                make_uint4(f2tf(wv.x), f2tf(wv.y), f2tf(wv.z), f2tf(wv.w));
        }
        __syncthreads();
#pragma unroll
        for (int ks = 0; ks < 4; ks++) {
            int kb = ks * 8;
            uint32_t a[2][4];
#pragma unroll
            for (int mf = 0; mf < 2; mf++) {
                int row = wm * 32 + mf * 16 + lr;
                a[mf][0] = sX[row * 36 + kb + lc];
                a[mf][1] = sX[(row + 8) * 36 + kb + lc];
                a[mf][2] = sX[row * 36 + kb + 4 + lc];
                a[mf][3] = sX[(row + 8) * 36 + kb + 4 + lc];
            }
#pragma unroll
            for (int nf = 0; nf < 8; nf++) {
                int col = wn * 64 + nf * 8 + lr;
                uint32_t b0 = sW[col * 36 + kb + lc];
                uint32_t b1 = sW[col * 36 + kb + 4 + lc];
                mma8(acc[0][nf], a[0], b0, b1);
                mma8(acc[1][nf], a[1], b0, b1);
            }
        }
        __syncthreads();
    }

#pragma unroll
    for (int mf = 0; mf < 2; mf++) {
#pragma unroll
        for (int nf = 0; nf < 8; nf++) {
            size_t row = m0 + wm * 32 + mf * 16 + lr;
            int col = wn * 64 + nf * 8 + 2 * lc;
            float b0v = __ldg(bias + col), b1v = __ldg(bias + col + 1);
            float v0 = acc[mf][nf][0] + b0v;
            float v1 = acc[mf][nf][1] + b1v;
            float v2 = acc[mf][nf][2] + b0v;
            float v3 = acc[mf][nf][3] + b1v;
            if (MODE == 1) {
                v0 = sigmoidf_(v0); v1 = sigmoidf_(v1);
                v2 = sigmoidf_(v2); v3 = sigmoidf_(v3);
            }
            if (MODE == 2) {
                v0 *= g_gate[row * 128 + col];       v1 *= g_gate[row * 128 + col + 1];
                v2 *= g_gate[(row + 8) * 128 + col]; v3 *= g_gate[(row + 8) * 128 + col + 1];
            }
            if (MODE == 3) {
                v0 *= g_Q[row * 128 + col];          v1 *= g_Q[row * 128 + col + 1];
                v2 *= g_Q[(row + 8) * 128 + col];    v3 *= g_Q[(row + 8) * 128 + col + 1];
            }
            *reinterpret_cast<float2*>(out + row * 128 + col)       = make_float2(v0, v1);
            *reinterpret_cast<float2*>(out + (row + 8) * 128 + col) = make_float2(v2, v3);
        }
    }
}

// ============================================================
// K3: transpose gated activation a -> [c][row].
// ============================================================
__global__ void act_transpose_kernel() {
    __shared__ float S[64][132];
    const size_t row0 = (size_t)blockIdx.x * 64;
    for (int idx = threadIdx.x; idx < 64 * 128; idx += 256) {
        int r = idx >> 7, c = idx & 127;
        S[r][c] = g_P[(row0 + r) * 128 + c];
    }
    __syncthreads();
    for (int idx = threadIdx.x; idx < 64 * 128; idx += 256) {
        int c = idx >> 6, r = idx & 63;
        g_at[(size_t)c * LL + row0 + r] = S[r][c];
    }
}

// ============================================================
// K4: tf32 tensor-core SYRK per channel: O_c = A_c A_c^T.
//     128x128 tiles, upper triangle (10 pairs) + mirror.
// ============================================================
__global__ void __launch_bounds__(256, 2)
syrk_mma() {
    __shared__ uint32_t sX[128 * 36];
    __shared__ uint32_t sW[128 * 36];
    const int tid  = threadIdx.x;
    const int wid  = tid >> 5, lane = tid & 31;
    const int wm   = wid >> 1, wn = wid & 1;
    const int lr   = lane >> 2, lc = lane & 3;

    const int c = blockIdx.y;
    int p = blockIdx.x;
    int bi = 0, rem = p, span = 4;
    while (rem >= span) { rem -= span; span--; bi++; }
    int bj = bi + rem;
    const int i0 = bi * 128, j0 = bj * 128;

    const float4* A4 = reinterpret_cast<const float4*>(g_at + (size_t)c * LL);
    float* __restrict__ O = g_o + (size_t)c * LL;

    float acc[2][8][4];
#pragma unroll
    for (int mf = 0; mf < 2; mf++)
#pragma unroll
        for (int nf = 0; nf < 8; nf++)
#pragma unroll
            for (int v = 0; v < 4; v++) acc[mf][nf][v] = 0.0f;

    for (int kc4 = 0; kc4 < 128; kc4 += 8) {   // K=512 in chunks of 32
#pragma unroll
        for (int e = 0; e < 4; e++) {
            int idx = tid + 256 * e;
            int r = idx >> 3, c4 = idx & 7;
            float4 xv = A4[(size_t)(i0 + r) * 128 + kc4 + c4];
            *reinterpret_cast<uint4*>(sX + r * 36 + c4 * 4) =
                make_uint4(f2tf(xv.x), f2tf(xv.y), f2tf(xv.z), f2tf(xv.w));
            float4 wv = A4[(size_t)(j0 + r) * 128 + kc4 + c4];
            *reinterpret_cast<uint4*>(sW + r * 36 + c4 * 4) =
                make_uint4(f2tf(wv.x), f2tf(wv.y), f2tf(wv.z), f2tf(wv.w));
        }
        __syncthreads();
#pragma unroll
        for (int ks = 0; ks < 4; ks++) {
            int kb = ks * 8;
            uint32_t a[2][4];
#pragma unroll
            for (int mf = 0; mf < 2; mf++) {
                int row = wm * 32 + mf * 16 + lr;
                a[mf][0] = sX[row * 36 + kb + lc];
                a[mf][1] = sX[(row + 8) * 36 + kb + lc];
                a[mf][2] = sX[row * 36 + kb + 4 + lc];
                a[mf][3] = sX[(row + 8) * 36 + kb + 4 + lc];
            }
#pragma unroll
            for (int nf = 0; nf < 8; nf++) {
                int col = wn * 64 + nf * 8 + lr;
                uint32_t b0 = sW[col * 36 + kb + lc];
                uint32_t b1 = sW[col * 36 + kb + 4 + lc];
                mma8(acc[0][nf], a[0], b0, b1);
                mma8(acc[1][nf], a[1], b0, b1);
            }
        }
        __syncthreads();
    }

    // direct tile write
#pragma unroll
    for (int mf = 0; mf < 2; mf++) {
#pragma unroll
        for (int nf = 0; nf < 8; nf++) {
            int rowi = i0 + wm * 32 + mf * 16 + lr;
            int colj = j0 + wn * 64 + nf * 8 + 2 * lc;
            *reinterpret_cast<float2*>(O + (size_t)rowi * 512 + colj) =
                make_float2(acc[mf][nf][0], acc[mf][nf][1]);
            *reinterpret_cast<float2*>(O + (size_t)(rowi + 8) * 512 + colj) =
                make_float2(acc[mf][nf][2], acc[mf][nf][3]);
        }
    }

    // mirror via smem transpose (warp wm owns rows [32*wm, 32*wm+32))
    if (bi != bj) {
#pragma unroll
        for (int sblk = 0; sblk < 4; sblk++) {
            __syncthreads();
            if (wm == sblk) {
#pragma unroll
                for (int mf = 0; mf < 2; mf++)
#pragma unroll
                    for (int nf = 0; nf < 8; nf++) {
                        int rl = mf * 16 + lr;
                        int col = wn * 64 + nf * 8 + 2 * lc;
                        sX[rl * 132 + col]           = __float_as_uint(acc[mf][nf][0]);
                        sX[rl * 132 + col + 1]       = __float_as_uint(acc[mf][nf][1]);
                        sX[(rl + 8) * 132 + col]     = __float_as_uint(acc[mf][nf][2]);
                        sX[(rl + 8) * 132 + col + 1] = __float_as_uint(acc[mf][nf][3]);
                    }
            }
            __syncthreads();
            for (int idx = tid; idx < 128 * 32; idx += 256) {
                int nn = idx >> 5, rl = idx & 31;
                O[(size_t)(j0 + nn) * 512 + i0 + sblk * 32 + rl] =
                    __uint_as_float(sX[rl * 132 + nn]);
            }
        }
    }
}

// ============================================================
// K5: transpose o[c][i][j] -> o2[(i,j)][c], fused LN over c.
// ============================================================
__global__ void trans_ln_kernel(const float* __restrict__ og,
                                const float* __restrict__ ob) {
    __shared__ float S[128][65];
    __shared__ float ps[4][64], pq[4][64];
    __shared__ float mS[64], rS[64];
    const int i  = blockIdx.y;
    const int j0 = blockIdx.x * 64;
    const int tid = threadIdx.x;

    for (int idx = tid; idx < 128 * 64; idx += 256) {
        int c = idx >> 6, jj = idx & 63;
        S[c][jj] = g_o[(size_t)c * LL + (size_t)i * 512 + j0 + jj];
    }
    __syncthreads();

    int col = tid & 63, grp = tid >> 6;
    float s = 0.0f, q = 0.0f;
    for (int c = grp; c < 128; c += 4) { float v = S[c][col]; s += v; q += v * v; }
    ps[grp][col] = s; pq[grp][col] = q;
    __syncthreads();
    if (tid < 64) {
        float ss = 0.0f, qq = 0.0f;
#pragma unroll
        for (int g2 = 0; g2 < 4; g2++) { ss += ps[g2][tid]; qq += pq[g2][tid]; }
        float mean = ss * (1.0f / 128.0f);
        float var  = qq * (1.0f / 128.0f) - mean * mean;
        mS[tid] = mean;
        rS[tid] = rsqrtf(var + 1e-5f);
    }
    __syncthreads();

    for (int idx = tid; idx < 128 * 64; idx += 256) {
        int jj = idx >> 7, c = idx & 127;
        float v = (S[c][jj] - mS[jj]) * rS[jj] * og[c] + ob[c];
        g_o2[((size_t)i * 512 + j0 + jj) * 128 + c] = v;
    }
}

// ============================================================
// launch
// ============================================================
extern "C" void kernel_launch(void* const* d_in, const int* in_sizes, int n_in,
                              void* d_out, int out_size) {
    const float* z      = (const float*)d_in[0];
    const float* norm_g = (const float*)d_in[1];
    const float* norm_b = (const float*)d_in[2];
    const float* a_w    = (const float*)d_in[3];
    const float* a_b    = (const float*)d_in[4];
    const float* ag_w   = (const float*)d_in[5];
    const float* ag_b   = (const float*)d_in[6];
    const float* onorm_g= (const float*)d_in[7];
    const float* onorm_b= (const float*)d_in[8];
    const float* o_w    = (const float*)d_in[9];
    const float* o_b    = (const float*)d_in[10];
    const float* g_wp   = (const float*)d_in[11];
    const float* g_bp   = (const float*)d_in[12];
    float* out = (float*)d_out;

    float *zn, *P, *Q, *gate, *o2;
    cudaGetSymbolAddress((void**)&zn,   g_zn);
    cudaGetSymbolAddress((void**)&P,    g_P);
    cudaGetSymbolAddress((void**)&Q,    g_Q);
    cudaGetSymbolAddress((void**)&gate, g_gate);
    cudaGetSymbolAddress((void**)&o2,   g_o2);

    ln_kernel<<<LL / 8, 256>>>(z, norm_g, norm_b);

    proj_mma<1><<<LL / 128, 256>>>(zn, ag_w, ag_b, Q);     // Q = sigmoid(zn@ag^T+b)
    proj_mma<3><<<LL / 128, 256>>>(zn, a_w,  a_b,  P);     // P = (zn@a^T+b) * Q
    proj_mma<1><<<LL / 128, 256>>>(zn, g_wp, g_bp, gate);  // gate = sigmoid(zn@g^T+b)

    act_transpose_kernel<<<LL / 64, 256>>>();

    syrk_mma<<<dim3(10, 128), 256>>>();

    trans_ln_kernel<<<dim3(8, L), 256>>>(onorm_g, onorm_b);

    proj_mma<2><<<LL / 128, 256>>>(o2, o_w, o_b, out);     // out = (o2@o_w^T+b) * gate
}

// round 3
// speedup vs baseline: 2.7438x; 1.1161x over previous
#include <cuda_runtime.h>
#include <math.h>
#include <stdint.h>

#define L 512
#define LL (L*L)

// ---- scratch (device globals; allocation-free contract) ----
__device__ float    g_gate[(size_t)LL*128]; // sigmoid(zn@g_w^T+g_b)   [row][z]
__device__ uint32_t g_at  [(size_t)128*LL]; // gated a, tf32 bits      [c][i*512+l]
__device__ float    g_o   [(size_t)128*LL]; // einsum output           [c][i*512+j]
__device__ uint32_t g_awt [128*128];        // tf32 weights
__device__ uint32_t g_agwt[128*128];
__device__ uint32_t g_gwt [128*128];
__device__ uint32_t g_owt [128*128];

__device__ __forceinline__ float sigmoidf_(float x) { return 1.0f / (1.0f + expf(-x)); }

__device__ __forceinline__ uint32_t f2tf(float f) {
    uint32_t u;
    asm("cvt.rna.tf32.f32 %0, %1;" : "=r"(u) : "f"(f));
    return u;
}

__device__ __forceinline__ void mma8(float* c, const uint32_t* a, uint32_t b0, uint32_t b1) {
    asm volatile(
        "mma.sync.aligned.m16n8k8.row.col.f32.tf32.tf32.f32 "
        "{%0,%1,%2,%3}, {%4,%5,%6,%7}, {%8,%9}, {%0,%1,%2,%3};\n"
        : "+f"(c[0]), "+f"(c[1]), "+f"(c[2]), "+f"(c[3])
        : "r"(a[0]), "r"(a[1]), "r"(a[2]), "r"(a[3]), "r"(b0), "r"(b1));
}

__device__ __forceinline__ void cpa16(void* dst, const void* src) {
    uint32_t s = (uint32_t)__cvta_generic_to_shared(dst);
    asm volatile("cp.async.cg.shared.global [%0], [%1], 16;\n" :: "r"(s), "l"(src));
}
__device__ __forceinline__ void cpa_commit() { asm volatile("cp.async.commit_group;\n" ::: "memory"); }
template<int N> __device__ __forceinline__ void cpa_wait() {
    asm volatile("cp.async.wait_group %0;\n" :: "n"(N) : "memory");
}

// ============================================================
// K0: pre-convert the 4 weight matrices to tf32 bits
// ============================================================
__global__ void prep_w(const float* __restrict__ aw, const float* __restrict__ agw,
                       const float* __restrict__ gw, const float* __restrict__ ow) {
    int idx = blockIdx.x * 256 + threadIdx.x;   // 65536 total
    int w = idx >> 14, i = idx & 16383;
    if (w == 0)      g_awt [i] = f2tf(aw[i]);
    else if (w == 1) g_agwt[i] = f2tf(agw[i]);
    else if (w == 2) g_gwt [i] = f2tf(gw[i]);
    else             g_owt [i] = f2tf(ow[i]);
}

// ============================================================
// K1: fused LN + (a, ag) dual GEMM + gating + transposed tf32
//     write of a, + gate GEMM. 128-row tile, K=128 in smem.
// ============================================================
__global__ void __launch_bounds__(256, 1)
fusedA(const float* __restrict__ z, const float* __restrict__ ng, const float* __restrict__ nb,
       const float* __restrict__ ab, const float* __restrict__ agb, const float* __restrict__ gb) {
    extern __shared__ uint32_t sm[];
    uint32_t* sZ  = sm;                 // 128*132 tf32 zn
    uint32_t* sWa = sm + 128 * 132;     // a_w, later g_w
    uint32_t* sWb = sm + 2 * 128 * 132; // ag_w, later P staging
    const int tid = threadIdx.x;
    const int wid = tid >> 5, lane = tid & 31;
    const int wm = wid >> 1, wn = wid & 1;
    const int lr = lane >> 2, lc = lane & 3;
    const size_t m0 = (size_t)blockIdx.x * 128;

    // async weight loads (overlap with LN)
#pragma unroll
    for (int e = 0; e < 16; e++) {
        int idx = tid + 256 * e;        // 4096 uint4 per weight
        int r = idx >> 5, c4 = idx & 31;
        cpa16(sWa + r * 132 + c4 * 4, g_awt  + r * 128 + c4 * 4);
        cpa16(sWb + r * 132 + c4 * 4, g_agwt + r * 128 + c4 * 4);
    }
    cpa_commit();

    // LayerNorm: warp w handles rows [16w, 16w+16)
    float4 g4 = reinterpret_cast<const float4*>(ng)[lane];
    float4 b4 = reinterpret_cast<const float4*>(nb)[lane];
    for (int it = 0; it < 16; it++) {
        int row = wid * 16 + it;
        float4 v = reinterpret_cast<const float4*>(z)[(m0 + row) * 32 + lane];
        float s = v.x + v.y + v.z + v.w;
        float q = v.x*v.x + v.y*v.y + v.z*v.z + v.w*v.w;
#pragma unroll
        for (int o = 16; o > 0; o >>= 1) {
            s += __shfl_xor_sync(0xffffffffu, s, o);
            q += __shfl_xor_sync(0xffffffffu, q, o);
        }
        float mean = s * (1.0f / 128.0f);
        float var  = q * (1.0f / 128.0f) - mean * mean;
        float rs   = rsqrtf(var + 1e-5f);
        uint4 o4 = make_uint4(f2tf((v.x - mean) * rs * g4.x + b4.x),
                              f2tf((v.y - mean) * rs * g4.y + b4.y),
                              f2tf((v.z - mean) * rs * g4.z + b4.z),
                              f2tf((v.w - mean) * rs * g4.w + b4.w));
        *reinterpret_cast<uint4*>(sZ + row * 132 + lane * 4) = o4;
    }
    cpa_wait<0>();
    __syncthreads();

    // ---- pass 1: dual GEMM (a_w and ag_w share A fragments) ----
    float acc_a[2][8][4], acc_q[2][8][4];
#pragma unroll
    for (int mf = 0; mf < 2; mf++)
#pragma unroll
        for (int nf = 0; nf < 8; nf++)
#pragma unroll
            for (int v = 0; v < 4; v++) { acc_a[mf][nf][v] = 0.0f; acc_q[mf][nf][v] = 0.0f; }

#pragma unroll
    for (int ks = 0; ks < 16; ks++) {
        int kb = ks * 8;
        uint32_t a[2][4];
#pragma unroll
        for (int mf = 0; mf < 2; mf++) {
            int row = wm * 32 + mf * 16 + lr;
            a[mf][0] = sZ[row * 132 + kb + lc];
            a[mf][1] = sZ[(row + 8) * 132 + kb + lc];
            a[mf][2] = sZ[row * 132 + kb + 4 + lc];
            a[mf][3] = sZ[(row + 8) * 132 + kb + 4 + lc];
        }
#pragma unroll
        for (int nf = 0; nf < 8; nf++) {
            int col = wn * 64 + nf * 8 + lr;
            uint32_t b0a = sWa[col * 132 + kb + lc];
            uint32_t b1a = sWa[col * 132 + kb + 4 + lc];
            uint32_t b0q = sWb[col * 132 + kb + lc];
            uint32_t b1q = sWb[col * 132 + kb + 4 + lc];
            mma8(acc_a[0][nf], a[0], b0a, b1a);
            mma8(acc_a[1][nf], a[1], b0a, b1a);
            mma8(acc_q[0][nf], a[0], b0q, b1q);
            mma8(acc_q[1][nf], a[1], b0q, b1q);
        }
    }
    __syncthreads();   // all reads of sWa/sWb done

    // prefetch g_w into sWa while we do the epilogue
#pragma unroll
    for (int e = 0; e < 16; e++) {
        int idx = tid + 256 * e;
        int r = idx >> 5, c4 = idx & 31;
        cpa16(sWa + r * 132 + c4 * 4, g_gwt + r * 128 + c4 * 4);
    }
    cpa_commit();

    // epilogue pass 1: P = (a + ab) * sigmoid(q + agb), staged transposed in sWb
    float* sP = reinterpret_cast<float*>(sWb);
#pragma unroll
    for (int mf = 0; mf < 2; mf++) {
#pragma unroll
        for (int nf = 0; nf < 8; nf++) {
            int rowl = wm * 32 + mf * 16 + lr;
            int col  = wn * 64 + nf * 8 + 2 * lc;
            float ba0 = __ldg(ab + col),  ba1 = __ldg(ab + col + 1);
            float bq0 = __ldg(agb + col), bq1 = __ldg(agb + col + 1);
            sP[col * 132 + rowl]           = (acc_a[mf][nf][0] + ba0) * sigmoidf_(acc_q[mf][nf][0] + bq0);
            sP[(col + 1) * 132 + rowl]     = (acc_a[mf][nf][1] + ba1) * sigmoidf_(acc_q[mf][nf][1] + bq1);
            sP[col * 132 + rowl + 8]       = (acc_a[mf][nf][2] + ba0) * sigmoidf_(acc_q[mf][nf][2] + bq0);
            sP[(col + 1) * 132 + rowl + 8] = (acc_a[mf][nf][3] + ba1) * sigmoidf_(acc_q[mf][nf][3] + bq1);
        }
    }
    __syncthreads();

    // write a transposed as tf32 bits (overlaps with g_w cp.async)
#pragma unroll
    for (int e = 0; e < 64; e++) {
        int idx = tid + 256 * e;        // 16384 elems
        int r = idx & 127, c = idx >> 7;
        g_at[(size_t)c * LL + m0 + r] = f2tf(sP[c * 132 + r]);
    }
    cpa_wait<0>();
    __syncthreads();

    // ---- pass 2: gate GEMM ----
#pragma unroll
    for (int mf = 0; mf < 2; mf++)
#pragma unroll
        for (int nf = 0; nf < 8; nf++)
#pragma unroll
            for (int v = 0; v < 4; v++) acc_a[mf][nf][v] = 0.0f;

#pragma unroll
    for (int ks = 0; ks < 16; ks++) {
        int kb = ks * 8;
        uint32_t a[2][4];
#pragma unroll
        for (int mf = 0; mf < 2; mf++) {
            int row = wm * 32 + mf * 16 + lr;
            a[mf][0] = sZ[row * 132 + kb + lc];
            a[mf][1] = sZ[(row + 8) * 132 + kb + lc];
            a[mf][2] = sZ[row * 132 + kb + 4 + lc];
            a[mf][3] = sZ[(row + 8) * 132 + kb + 4 + lc];
        }
#pragma unroll
        for (int nf = 0; nf < 8; nf++) {
            int col = wn * 64 + nf * 8 + lr;
            uint32_t b0 = sWa[col * 132 + kb + lc];
            uint32_t b1 = sWa[col * 132 + kb + 4 + lc];
            mma8(acc_a[0][nf], a[0], b0, b1);
            mma8(acc_a[1][nf], a[1], b0, b1);
        }
    }

#pragma unroll
    for (int mf = 0; mf < 2; mf++) {
#pragma unroll
        for (int nf = 0; nf < 8; nf++) {
            size_t row = m0 + wm * 32 + mf * 16 + lr;
            int col = wn * 64 + nf * 8 + 2 * lc;
            float b0v = __ldg(gb + col), b1v = __ldg(gb + col + 1);
            *reinterpret_cast<float2*>(g_gate + row * 128 + col) =
                make_float2(sigmoidf_(acc_a[mf][nf][0] + b0v), sigmoidf_(acc_a[mf][nf][1] + b1v));
            *reinterpret_cast<float2*>(g_gate + (row + 8) * 128 + col) =
                make_float2(sigmoidf_(acc_a[mf][nf][2] + b0v), sigmoidf_(acc_a[mf][nf][3] + b1v));
        }
    }
}

// ============================================================
// K2: tf32 SYRK per channel, cp.async double-buffered.
// ============================================================
__global__ void __launch_bounds__(256, 2)
syrk_mma() {
    extern __shared__ uint32_t sm[];   // 2 buffers x (A 4608 + B 4608) uint32
    const int tid  = threadIdx.x;
    const int wid  = tid >> 5, lane = tid & 31;
    const int wm   = wid >> 1, wn = wid & 1;
    const int lr   = lane >> 2, lc = lane & 3;

    const int c = blockIdx.y;
    int rem = blockIdx.x, bi = 0, span = 4;
    while (rem >= span) { rem -= span; span--; bi++; }
    int bj = bi + rem;
    const int i0 = bi * 128, j0 = bj * 128;
    const bool diag = (bi == bj);

    const uint32_t* __restrict__ Ag = g_at + (size_t)c * LL;
    float* __restrict__ O = g_o + (size_t)c * LL;

    auto load_chunk = [&](int kc, int buf) {
        uint32_t* sA = sm + buf * 9216;
        uint32_t* sB = sA + 4608;
#pragma unroll
        for (int e = 0; e < 4; e++) {
            int idx = tid + 256 * e;   // 1024 uint4
            int r = idx >> 3, c4 = idx & 7;
            cpa16(sA + r * 36 + c4 * 4, Ag + (size_t)(i0 + r) * 512 + kc * 32 + c4 * 4);
            if (!diag)
                cpa16(sB + r * 36 + c4 * 4, Ag + (size_t)(j0 + r) * 512 + kc * 32 + c4 * 4);
        }
        cpa_commit();
    };

    float acc[2][8][4];
#pragma unroll
    for (int mf = 0; mf < 2; mf++)
#pragma unroll
        for (int nf = 0; nf < 8; nf++)
#pragma unroll
            for (int v = 0; v < 4; v++) acc[mf][nf][v] = 0.0f;

    load_chunk(0, 0);

    for (int kc = 0; kc < 16; kc++) {
        if (kc + 1 < 16) { load_chunk(kc + 1, (kc + 1) & 1); cpa_wait<1>(); }
        else             { cpa_wait<0>(); }
        __syncthreads();
        const uint32_t* sA = sm + (kc & 1) * 9216;
        const uint32_t* sB = diag ? sA : sA + 4608;
#pragma unroll
        for (int ks = 0; ks < 4; ks++) {
            int kb = ks * 8;
            uint32_t a[2][4];
#pragma unroll
            for (int mf = 0; mf < 2; mf++) {
                int row = wm * 32 + mf * 16 + lr;
                a[mf][0] = sA[row * 36 + kb + lc];
                a[mf][1] = sA[(row + 8) * 36 + kb + lc];
                a[mf][2] = sA[row * 36 + kb + 4 + lc];
                a[mf][3] = sA[(row + 8) * 36 + kb + 4 + lc];
            }
#pragma unroll
            for (int nf = 0; nf < 8; nf++) {
                int col = wn * 64 + nf * 8 + lr;
                uint32_t b0 = sB[col * 36 + kb + lc];
                uint32_t b1 = sB[col * 36 + kb + 4 + lc];
                mma8(acc[0][nf], a[0], b0, b1);
                mma8(acc[1][nf], a[1], b0, b1);
            }
        }
        __syncthreads();
    }

    // direct tile write
#pragma unroll
    for (int mf = 0; mf < 2; mf++) {
#pragma unroll
        for (int nf = 0; nf < 8; nf++) {
            int rowi = i0 + wm * 32 + mf * 16 + lr;
            int colj = j0 + wn * 64 + nf * 8 + 2 * lc;
            *reinterpret_cast<float2*>(O + (size_t)rowi * 512 + colj) =
                make_float2(acc[mf][nf][0], acc[mf][nf][1]);
            *reinterpret_cast<float2*>(O + (size_t)(rowi + 8) * 512 + colj) =
                make_float2(acc[mf][nf][2], acc[mf][nf][3]);
        }
    }

    // mirror via smem transpose staging
    if (!diag) {
        float* st = reinterpret_cast<float*>(sm);
#pragma unroll
        for (int sblk = 0; sblk < 4; sblk++) {
            __syncthreads();
            if (wm == sblk) {
#pragma unroll
                for (int mf = 0; mf < 2; mf++)
#pragma unroll
                    for (int nf = 0; nf < 8; nf++) {
                        int rl = mf * 16 + lr;
                        int col = wn * 64 + nf * 8 + 2 * lc;
                        st[rl * 132 + col]           = acc[mf][nf][0];
                        st[rl * 132 + col + 1]       = acc[mf][nf][1];
                        st[(rl + 8) * 132 + col]     = acc[mf][nf][2];
                        st[(rl + 8) * 132 + col + 1] = acc[mf][nf][3];
                    }
            }
            __syncthreads();
            for (int idx = tid; idx < 128 * 32; idx += 256) {
                int nn = idx >> 5, rl = idx & 31;
                O[(size_t)(j0 + nn) * 512 + i0 + sblk * 32 + rl] = st[rl * 132 + nn];
            }
        }
    }
}

// ============================================================
// K3: fused gather + channel-LN + final projection + gating.
//     block = (i, 128 j's). 128 output rows, K=128 channels.
// ============================================================
__global__ void __launch_bounds__(256, 1)
fusedC(const float* __restrict__ ong, const float* __restrict__ onb,
       const float* __restrict__ ob, float* __restrict__ out) {
    extern __shared__ uint32_t sm[];
    float*    sO = reinterpret_cast<float*>(sm);   // [c][jj], pitch 132
    uint32_t* sW = sm + 128 * 132;
    __shared__ float ps[2][128], pq[2][128], mS[128], rS[128];

    const int tid = threadIdx.x;
    const int wid = tid >> 5, lane = tid & 31;
    const int wm = wid >> 1, wn = wid & 1;
    const int lr = lane >> 2, lc = lane & 3;
    const int i = blockIdx.y, j0 = blockIdx.x * 128;

    // async o_w load
#pragma unroll
    for (int e = 0; e < 16; e++) {
        int idx = tid + 256 * e;
        int r = idx >> 5, c4 = idx & 31;
        cpa16(sW + r * 132 + c4 * 4, g_owt + r * 128 + c4 * 4);
    }
    cpa_commit();

    // gather o tile [c][jj] (coalesced 512B rows)
#pragma unroll
    for (int e = 0; e < 16; e++) {
        int idx = tid + 256 * e;       // 4096 float4
        int c = idx >> 5, j4 = idx & 31;
        float4 v = reinterpret_cast<const float4*>(g_o + (size_t)c * LL + (size_t)i * 512 + j0)[j4];
        *reinterpret_cast<float4*>(sO + c * 132 + j4 * 4) = v;
    }
    __syncthreads();

    // channel reduce (2 partials per column)
    {
        int col = tid & 127, half = tid >> 7;
        float s = 0.0f, q = 0.0f;
        for (int c = half * 64; c < half * 64 + 64; c++) {
            float v = sO[c * 132 + col];
            s += v; q += v * v;
        }
        ps[half][col] = s; pq[half][col] = q;
    }
    __syncthreads();
    if (tid < 128) {
        float ss = ps[0][tid] + ps[1][tid];
        float qq = pq[0][tid] + pq[1][tid];
        float mean = ss * (1.0f / 128.0f);
        float var  = qq * (1.0f / 128.0f) - mean * mean;
        mS[tid] = mean;
        rS[tid] = rsqrtf(var + 1e-5f);
    }
    __syncthreads();

    // normalize in place -> tf32 bits
#pragma unroll
    for (int e = 0; e < 64; e++) {
        int idx = tid + 256 * e;
        int jj = idx & 127, c = idx >> 7;
        float v = (sO[c * 132 + jj] - mS[jj]) * rS[jj] * __ldg(ong + c) + __ldg(onb + c);
        sm[c * 132 + jj] = f2tf(v);
    }
    __syncthreads();

    // GEMM: rows = jj (X read transposed from [c][jj]), K = c
    float acc[2][8][4];
#pragma unroll
    for (int mf = 0; mf < 2; mf++)
#pragma unroll
        for (int nf = 0; nf < 8; nf++)
#pragma unroll
            for (int v = 0; v < 4; v++) acc[mf][nf][v] = 0.0f;

#pragma unroll
    for (int ks = 0; ks < 16; ks++) {
        int kb = ks * 8;
        uint32_t a[2][4];
#pragma unroll
        for (int mf = 0; mf < 2; mf++) {
            int row = wm * 32 + mf * 16 + lr;
            a[mf][0] = sm[(kb + lc) * 132 + row];
            a[mf][1] = sm[(kb + lc) * 132 + row + 8];
            a[mf][2] = sm[(kb + 4 + lc) * 132 + row];
            a[mf][3] = sm[(kb + 4 + lc) * 132 + row + 8];
        }
#pragma unroll
        for (int nf = 0; nf < 8; nf++) {
            int col = wn * 64 + nf * 8 + lr;
            uint32_t b0 = sW[col * 132 + kb + lc];
            uint32_t b1 = sW[col * 132 + kb + 4 + lc];
            mma8(acc[0][nf], a[0], b0, b1);
            mma8(acc[1][nf], a[1], b0, b1);
        }
    }

    const size_t grow = (size_t)i * 512 + j0;
#pragma unroll
    for (int mf = 0; mf < 2; mf++) {
#pragma unroll
        for (int nf = 0; nf < 8; nf++) {
            size_t row = grow + wm * 32 + mf * 16 + lr;
            int col = wn * 64 + nf * 8 + 2 * lc;
            float b0v = __ldg(ob + col), b1v = __ldg(ob + col + 1);
            float2 gt0 = *reinterpret_cast<const float2*>(g_gate + row * 128 + col);
            float2 gt1 = *reinterpret_cast<const float2*>(g_gate + (row + 8) * 128 + col);
            *reinterpret_cast<float2*>(out + row * 128 + col) =
                make_float2((acc[mf][nf][0] + b0v) * gt0.x, (acc[mf][nf][1] + b1v) * gt0.y);
            *reinterpret_cast<float2*>(out + (row + 8) * 128 + col) =
                make_float2((acc[mf][nf][2] + b0v) * gt1.x, (acc[mf][nf][3] + b1v) * gt1.y);
        }
    }
}

// ============================================================
// launch
// ============================================================
extern "C" void kernel_launch(void* const* d_in, const int* in_sizes, int n_in,
                              void* d_out, int out_size) {
    const float* z      = (const float*)d_in[0];
    const float* norm_g = (const float*)d_in[1];
    const float* norm_b = (const float*)d_in[2];
    const float* a_w    = (const float*)d_in[3];
    const float* a_b    = (const float*)d_in[4];
    const float* ag_w   = (const float*)d_in[5];
    const float* ag_b   = (const float*)d_in[6];
    const float* onorm_g= (const float*)d_in[7];
    const float* onorm_b= (const float*)d_in[8];
    const float* o_w    = (const float*)d_in[9];
    const float* o_b    = (const float*)d_in[10];
    const float* g_wp   = (const float*)d_in[11];
    const float* g_bp   = (const float*)d_in[12];
    float* out = (float*)d_out;

    static bool attr_done = false;
    if (!attr_done) {
        cudaFuncSetAttribute(fusedA,   cudaFuncAttributeMaxDynamicSharedMemorySize, 3 * 128 * 132 * 4);
        cudaFuncSetAttribute(syrk_mma, cudaFuncAttributeMaxDynamicSharedMemorySize, 2 * 9216 * 4);
        cudaFuncSetAttribute(fusedC,   cudaFuncAttributeMaxDynamicSharedMemorySize, 2 * 128 * 132 * 4);
        attr_done = true;
    }

    prep_w<<<256, 256>>>(a_w, ag_w, g_wp, o_w);
    fusedA<<<LL / 128, 256, 3 * 128 * 132 * 4>>>(z, norm_g, norm_b, a_b, ag_b, g_bp);
    syrk_mma<<<dim3(10, 128), 256, 2 * 9216 * 4>>>();
    fusedC<<<dim3(4, L), 256, 2 * 128 * 132 * 4>>>(onorm_g, onorm_b, o_b, out);
}

// round 4
// speedup vs baseline: 3.3480x; 1.2202x over previous
#include <cuda_runtime.h>
#include <math.h>
#include <stdint.h>

#define L 512
#define LL (L*L)

// ---- scratch (device globals; allocation-free contract) ----
__device__ float    g_gate[(size_t)LL*128]; // sigmoid(zn@g_w^T+g_b)   [row][z]
__device__ uint32_t g_at  [(size_t)128*LL]; // gated a, tf32 bits      [c][i*512+l]
__device__ float    g_o   [(size_t)128*LL]; // einsum output           [c][i*512+j]
__device__ uint32_t g_awt [128*128];        // tf32 weights
__device__ uint32_t g_agwt[128*128];
__device__ uint32_t g_gwt [128*128];
__device__ uint32_t g_owt [128*128];

__device__ __forceinline__ float sigmoidf_(float x) { return 1.0f / (1.0f + expf(-x)); }

__device__ __forceinline__ uint32_t f2tf(float f) {
    uint32_t u;
    asm("cvt.rna.tf32.f32 %0, %1;" : "=r"(u) : "f"(f));
    return u;
}

__device__ __forceinline__ void mma8(float* c, const uint32_t* a, uint32_t b0, uint32_t b1) {
    asm volatile(
        "mma.sync.aligned.m16n8k8.row.col.f32.tf32.tf32.f32 "
        "{%0,%1,%2,%3}, {%4,%5,%6,%7}, {%8,%9}, {%0,%1,%2,%3};\n"
        : "+f"(c[0]), "+f"(c[1]), "+f"(c[2]), "+f"(c[3])
        : "r"(a[0]), "r"(a[1]), "r"(a[2]), "r"(a[3]), "r"(b0), "r"(b1));
}

__device__ __forceinline__ void cpa16(void* dst, const void* src) {
    uint32_t s = (uint32_t)__cvta_generic_to_shared(dst);
    asm volatile("cp.async.cg.shared.global [%0], [%1], 16;\n" :: "r"(s), "l"(src));
}
__device__ __forceinline__ void cpa_commit() { asm volatile("cp.async.commit_group;\n" ::: "memory"); }
template<int N> __device__ __forceinline__ void cpa_wait() {
    asm volatile("cp.async.wait_group %0;\n" :: "n"(N) : "memory");
}

// ============================================================
// K0: pre-convert the 4 weight matrices to tf32 bits
// ============================================================
__global__ void prep_w(const float* __restrict__ aw, const float* __restrict__ agw,
                       const float* __restrict__ gw, const float* __restrict__ ow) {
    int idx = blockIdx.x * 512 + threadIdx.x;   // 65536 total
    int w = idx >> 14, i = idx & 16383;
    if (w == 0)      g_awt [i] = f2tf(aw[i]);
    else if (w == 1) g_agwt[i] = f2tf(agw[i]);
    else if (w == 2) g_gwt [i] = f2tf(gw[i]);
    else             g_owt [i] = f2tf(ow[i]);
}

// ============================================================
// K1: fused LN + dual GEMM (a, ag) + gating + transposed tf32
//     write of a, + gate GEMM. 512 thr, 4x4 warps, 32x32 tile.
// ============================================================
__global__ void __launch_bounds__(512, 1)
fusedA(const float* __restrict__ z, const float* __restrict__ ng, const float* __restrict__ nb,
       const float* __restrict__ ab, const float* __restrict__ agb, const float* __restrict__ gb) {
    extern __shared__ uint32_t sm[];
    uint32_t* sZ  = sm;                 // 128*132 tf32 zn
    uint32_t* sWa = sm + 128 * 132;     // a_w, later g_w
    uint32_t* sWb = sm + 2 * 128 * 132; // ag_w, later P staging
    const int tid = threadIdx.x;
    const int wid = tid >> 5, lane = tid & 31;
    const int wm = wid >> 2, wn = wid & 3;
    const int lr = lane >> 2, lc = lane & 3;
    const size_t m0 = (size_t)blockIdx.x * 128;

    // async weight loads (overlap with LN)
#pragma unroll
    for (int e = 0; e < 8; e++) {
        int idx = tid + 512 * e;        // 4096 uint4 per weight
        int r = idx >> 5, c4 = idx & 31;
        cpa16(sWa + r * 132 + c4 * 4, g_awt  + r * 128 + c4 * 4);
        cpa16(sWb + r * 132 + c4 * 4, g_agwt + r * 128 + c4 * 4);
    }
    cpa_commit();

    // LayerNorm: warp w handles rows [8w, 8w+8)
    float4 g4 = reinterpret_cast<const float4*>(ng)[lane];
    float4 b4 = reinterpret_cast<const float4*>(nb)[lane];
    for (int it = 0; it < 8; it++) {
        int row = wid * 8 + it;
        float4 v = reinterpret_cast<const float4*>(z)[(m0 + row) * 32 + lane];
        float s = v.x + v.y + v.z + v.w;
        float q = v.x*v.x + v.y*v.y + v.z*v.z + v.w*v.w;
#pragma unroll
        for (int o = 16; o > 0; o >>= 1) {
            s += __shfl_xor_sync(0xffffffffu, s, o);
            q += __shfl_xor_sync(0xffffffffu, q, o);
        }
        float mean = s * (1.0f / 128.0f);
        float var  = q * (1.0f / 128.0f) - mean * mean;
        float rs   = rsqrtf(var + 1e-5f);
        uint4 o4 = make_uint4(f2tf((v.x - mean) * rs * g4.x + b4.x),
                              f2tf((v.y - mean) * rs * g4.y + b4.y),
                              f2tf((v.z - mean) * rs * g4.z + b4.z),
                              f2tf((v.w - mean) * rs * g4.w + b4.w));
        *reinterpret_cast<uint4*>(sZ + row * 132 + lane * 4) = o4;
    }
    cpa_wait<0>();
    __syncthreads();

    // ---- pass 1: dual GEMM (a_w and ag_w share A fragments) ----
    float acc_a[2][4][4], acc_q[2][4][4];
#pragma unroll
    for (int mf = 0; mf < 2; mf++)
#pragma unroll
        for (int nf = 0; nf < 4; nf++)
#pragma unroll
            for (int v = 0; v < 4; v++) { acc_a[mf][nf][v] = 0.0f; acc_q[mf][nf][v] = 0.0f; }

#pragma unroll
    for (int ks = 0; ks < 16; ks++) {
        int kb = ks * 8;
        uint32_t a[2][4];
#pragma unroll
        for (int mf = 0; mf < 2; mf++) {
            int row = wm * 32 + mf * 16 + lr;
            a[mf][0] = sZ[row * 132 + kb + lc];
            a[mf][1] = sZ[(row + 8) * 132 + kb + lc];
            a[mf][2] = sZ[row * 132 + kb + 4 + lc];
            a[mf][3] = sZ[(row + 8) * 132 + kb + 4 + lc];
        }
#pragma unroll
        for (int nf = 0; nf < 4; nf++) {
            int col = wn * 32 + nf * 8 + lr;
            uint32_t b0a = sWa[col * 132 + kb + lc];
            uint32_t b1a = sWa[col * 132 + kb + 4 + lc];
            uint32_t b0q = sWb[col * 132 + kb + lc];
            uint32_t b1q = sWb[col * 132 + kb + 4 + lc];
            mma8(acc_a[0][nf], a[0], b0a, b1a);
            mma8(acc_a[1][nf], a[1], b0a, b1a);
            mma8(acc_q[0][nf], a[0], b0q, b1q);
            mma8(acc_q[1][nf], a[1], b0q, b1q);
        }
    }
    __syncthreads();   // all reads of sWa/sWb done

    // prefetch g_w into sWa while we do the epilogue
#pragma unroll
    for (int e = 0; e < 8; e++) {
        int idx = tid + 512 * e;
        int r = idx >> 5, c4 = idx & 31;
        cpa16(sWa + r * 132 + c4 * 4, g_gwt + r * 128 + c4 * 4);
    }
    cpa_commit();

    // epilogue pass 1: P = (a + ab) * sigmoid(q + agb), staged transposed in sWb
    float* sP = reinterpret_cast<float*>(sWb);
#pragma unroll
    for (int mf = 0; mf < 2; mf++) {
#pragma unroll
        for (int nf = 0; nf < 4; nf++) {
            int rowl = wm * 32 + mf * 16 + lr;
            int col  = wn * 32 + nf * 8 + 2 * lc;
            float ba0 = __ldg(ab + col),  ba1 = __ldg(ab + col + 1);
            float bq0 = __ldg(agb + col), bq1 = __ldg(agb + col + 1);
            sP[col * 132 + rowl]           = (acc_a[mf][nf][0] + ba0) * sigmoidf_(acc_q[mf][nf][0] + bq0);
            sP[(col + 1) * 132 + rowl]     = (acc_a[mf][nf][1] + ba1) * sigmoidf_(acc_q[mf][nf][1] + bq1);
            sP[col * 132 + rowl + 8]       = (acc_a[mf][nf][2] + ba0) * sigmoidf_(acc_q[mf][nf][2] + bq0);
            sP[(col + 1) * 132 + rowl + 8] = (acc_a[mf][nf][3] + ba1) * sigmoidf_(acc_q[mf][nf][3] + bq1);
        }
    }
    __syncthreads();

    // write a transposed as tf32 bits (overlaps with g_w cp.async)
#pragma unroll 8
    for (int e = 0; e < 32; e++) {
        int idx = tid + 512 * e;        // 16384 elems
        int r = idx & 127, c = idx >> 7;
        g_at[(size_t)c * LL + m0 + r] = f2tf(sP[c * 132 + r]);
    }
    cpa_wait<0>();
    __syncthreads();

    // ---- pass 2: gate GEMM ----
#pragma unroll
    for (int mf = 0; mf < 2; mf++)
#pragma unroll
        for (int nf = 0; nf < 4; nf++)
#pragma unroll
            for (int v = 0; v < 4; v++) acc_a[mf][nf][v] = 0.0f;

#pragma unroll
    for (int ks = 0; ks < 16; ks++) {
        int kb = ks * 8;
        uint32_t a[2][4];
#pragma unroll
        for (int mf = 0; mf < 2; mf++) {
            int row = wm * 32 + mf * 16 + lr;
            a[mf][0] = sZ[row * 132 + kb + lc];
            a[mf][1] = sZ[(row + 8) * 132 + kb + lc];
            a[mf][2] = sZ[row * 132 + kb + 4 + lc];
            a[mf][3] = sZ[(row + 8) * 132 + kb + 4 + lc];
        }
#pragma unroll
        for (int nf = 0; nf < 4; nf++) {
            int col = wn * 32 + nf * 8 + lr;
            uint32_t b0 = sWa[col * 132 + kb + lc];
            uint32_t b1 = sWa[col * 132 + kb + 4 + lc];
            mma8(acc_a[0][nf], a[0], b0, b1);
            mma8(acc_a[1][nf], a[1], b0, b1);
        }
    }

#pragma unroll
    for (int mf = 0; mf < 2; mf++) {
#pragma unroll
        for (int nf = 0; nf < 4; nf++) {
            size_t row = m0 + wm * 32 + mf * 16 + lr;
            int col = wn * 32 + nf * 8 + 2 * lc;
            float b0v = __ldg(gb + col), b1v = __ldg(gb + col + 1);
            *reinterpret_cast<float2*>(g_gate + row * 128 + col) =
                make_float2(sigmoidf_(acc_a[mf][nf][0] + b0v), sigmoidf_(acc_a[mf][nf][1] + b1v));
            *reinterpret_cast<float2*>(g_gate + (row + 8) * 128 + col) =
                make_float2(sigmoidf_(acc_a[mf][nf][2] + b0v), sigmoidf_(acc_a[mf][nf][3] + b1v));
        }
    }
}

// ============================================================
// K2: tf32 SYRK per channel, cp.async double-buffered. 256 thr.
// ============================================================
__global__ void __launch_bounds__(256, 2)
syrk_mma() {
    extern __shared__ uint32_t sm[];   // 2 buffers x (A 4608 + B 4608) uint32
    const int tid  = threadIdx.x;
    const int wid  = tid >> 5, lane = tid & 31;
    const int wm   = wid >> 1, wn = wid & 1;
    const int lr   = lane >> 2, lc = lane & 3;

    const int c = blockIdx.y;
    int rem = blockIdx.x, bi = 0, span = 4;
    while (rem >= span) { rem -= span; span--; bi++; }
    int bj = bi + rem;
    const int i0 = bi * 128, j0 = bj * 128;
    const bool diag = (bi == bj);

    const uint32_t* __restrict__ Ag = g_at + (size_t)c * LL;
    float* __restrict__ O = g_o + (size_t)c * LL;

    auto load_chunk = [&](int kc, int buf) {
        uint32_t* sA = sm + buf * 9216;
        uint32_t* sB = sA + 4608;
#pragma unroll
        for (int e = 0; e < 4; e++) {
            int idx = tid + 256 * e;   // 1024 uint4
            int r = idx >> 3, c4 = idx & 7;
            cpa16(sA + r * 36 + c4 * 4, Ag + (size_t)(i0 + r) * 512 + kc * 32 + c4 * 4);
            if (!diag)
                cpa16(sB + r * 36 + c4 * 4, Ag + (size_t)(j0 + r) * 512 + kc * 32 + c4 * 4);
        }
        cpa_commit();
    };

    float acc[2][8][4];
#pragma unroll
    for (int mf = 0; mf < 2; mf++)
#pragma unroll
        for (int nf = 0; nf < 8; nf++)
#pragma unroll
            for (int v = 0; v < 4; v++) acc[mf][nf][v] = 0.0f;

    load_chunk(0, 0);

    for (int kc = 0; kc < 16; kc++) {
        if (kc + 1 < 16) { load_chunk(kc + 1, (kc + 1) & 1); cpa_wait<1>(); }
        else             { cpa_wait<0>(); }
        __syncthreads();
        const uint32_t* sA = sm + (kc & 1) * 9216;
        const uint32_t* sB = diag ? sA : sA + 4608;
#pragma unroll
        for (int ks = 0; ks < 4; ks++) {
            int kb = ks * 8;
            uint32_t a[2][4];
#pragma unroll
            for (int mf = 0; mf < 2; mf++) {
                int row = wm * 32 + mf * 16 + lr;
                a[mf][0] = sA[row * 36 + kb + lc];
                a[mf][1] = sA[(row + 8) * 36 + kb + lc];
                a[mf][2] = sA[row * 36 + kb + 4 + lc];
                a[mf][3] = sA[(row + 8) * 36 + kb + 4 + lc];
            }
#pragma unroll
            for (int nf = 0; nf < 8; nf++) {
                int col = wn * 64 + nf * 8 + lr;
                uint32_t b0 = sB[col * 36 + kb + lc];
                uint32_t b1 = sB[col * 36 + kb + 4 + lc];
                mma8(acc[0][nf], a[0], b0, b1);
                mma8(acc[1][nf], a[1], b0, b1);
            }
        }
        __syncthreads();
    }

    // direct tile write
#pragma unroll
    for (int mf = 0; mf < 2; mf++) {
#pragma unroll
        for (int nf = 0; nf < 8; nf++) {
            int rowi = i0 + wm * 32 + mf * 16 + lr;
            int colj = j0 + wn * 64 + nf * 8 + 2 * lc;
            *reinterpret_cast<float2*>(O + (size_t)rowi * 512 + colj) =
                make_float2(acc[mf][nf][0], acc[mf][nf][1]);
            *reinterpret_cast<float2*>(O + (size_t)(rowi + 8) * 512 + colj) =
                make_float2(acc[mf][nf][2], acc[mf][nf][3]);
        }
    }

    // mirror via smem transpose staging
    if (!diag) {
        float* st = reinterpret_cast<float*>(sm);
#pragma unroll
        for (int sblk = 0; sblk < 4; sblk++) {
            __syncthreads();
            if (wm == sblk) {
#pragma unroll
                for (int mf = 0; mf < 2; mf++)
#pragma unroll
                    for (int nf = 0; nf < 8; nf++) {
                        int rl = mf * 16 + lr;
                        int col = wn * 64 + nf * 8 + 2 * lc;
                        st[rl * 132 + col]           = acc[mf][nf][0];
                        st[rl * 132 + col + 1]       = acc[mf][nf][1];
                        st[(rl + 8) * 132 + col]     = acc[mf][nf][2];
                        st[(rl + 8) * 132 + col + 1] = acc[mf][nf][3];
                    }
            }
            __syncthreads();
#pragma unroll 4
            for (int idx = tid; idx < 128 * 32; idx += 256) {
                int nn = idx >> 5, rl = idx & 31;
                O[(size_t)(j0 + nn) * 512 + i0 + sblk * 32 + rl] = st[rl * 132 + nn];
            }
        }
    }
}

// ============================================================
// K3: fused gather + channel-LN + final projection + gating.
//     512 thr, 4x4 warps, 32x32 warp tile.
// ============================================================
__global__ void __launch_bounds__(512, 1)
fusedC(const float* __restrict__ ong, const float* __restrict__ onb,
       const float* __restrict__ ob, float* __restrict__ out) {
    extern __shared__ uint32_t sm[];
    float*    sO = reinterpret_cast<float*>(sm);   // [c][jj], pitch 132
    uint32_t* sW = sm + 128 * 132;
    __shared__ float ps[4][128], pq[4][128], mS[128], rS[128];

    const int tid = threadIdx.x;
    const int wid = tid >> 5, lane = tid & 31;
    const int wm = wid >> 2, wn = wid & 3;
    const int lr = lane >> 2, lc = lane & 3;
    const int i = blockIdx.y, j0 = blockIdx.x * 128;

    // async o_w load
#pragma unroll
    for (int e = 0; e < 8; e++) {
        int idx = tid + 512 * e;
        int r = idx >> 5, c4 = idx & 31;
        cpa16(sW + r * 132 + c4 * 4, g_owt + r * 128 + c4 * 4);
    }
    cpa_commit();

    // gather o tile [c][jj] (coalesced 512B rows)
#pragma unroll
    for (int e = 0; e < 8; e++) {
        int idx = tid + 512 * e;       // 4096 float4
        int c = idx >> 5, j4 = idx & 31;
        float4 v = reinterpret_cast<const float4*>(g_o + (size_t)c * LL + (size_t)i * 512 + j0)[j4];
        *reinterpret_cast<float4*>(sO + c * 132 + j4 * 4) = v;
    }
    __syncthreads();

    // channel reduce (4 partials per column)
    {
        int col = tid & 127, qtr = tid >> 7;
        float s = 0.0f, q = 0.0f;
#pragma unroll 8
        for (int c = qtr * 32; c < qtr * 32 + 32; c++) {
            float v = sO[c * 132 + col];
            s += v; q += v * v;
        }
        ps[qtr][col] = s; pq[qtr][col] = q;
    }
    __syncthreads();
    if (tid < 128) {
        float ss = ps[0][tid] + ps[1][tid] + ps[2][tid] + ps[3][tid];
        float qq = pq[0][tid] + pq[1][tid] + pq[2][tid] + pq[3][tid];
        float mean = ss * (1.0f / 128.0f);
        float var  = qq * (1.0f / 128.0f) - mean * mean;
        mS[tid] = mean;
        rS[tid] = rsqrtf(var + 1e-5f);
    }
    __syncthreads();

    // normalize in place -> tf32 bits
#pragma unroll 8
    for (int e = 0; e < 32; e++) {
        int idx = tid + 512 * e;
        int jj = idx & 127, c = idx >> 7;
        float v = (sO[c * 132 + jj] - mS[jj]) * rS[jj] * __ldg(ong + c) + __ldg(onb + c);
        sm[c * 132 + jj] = f2tf(v);
    }
    __syncthreads();

    // GEMM: rows = jj (X read transposed from [c][jj]), K = c
    float acc[2][4][4];
#pragma unroll
    for (int mf = 0; mf < 2; mf++)
#pragma unroll
        for (int nf = 0; nf < 4; nf++)
#pragma unroll
            for (int v = 0; v < 4; v++) acc[mf][nf][v] = 0.0f;

#pragma unroll
    for (int ks = 0; ks < 16; ks++) {
        int kb = ks * 8;
        uint32_t a[2][4];
#pragma unroll
        for (int mf = 0; mf < 2; mf++) {
            int row = wm * 32 + mf * 16 + lr;
            a[mf][0] = sm[(kb + lc) * 132 + row];
            a[mf][1] = sm[(kb + lc) * 132 + row + 8];
            a[mf][2] = sm[(kb + 4 + lc) * 132 + row];
            a[mf][3] = sm[(kb + 4 + lc) * 132 + row + 8];
        }
#pragma unroll
        for (int nf = 0; nf < 4; nf++) {
            int col = wn * 32 + nf * 8 + lr;
            uint32_t b0 = sW[col * 132 + kb + lc];
            uint32_t b1 = sW[col * 132 + kb + 4 + lc];
            mma8(acc[0][nf], a[0], b0, b1);
            mma8(acc[1][nf], a[1], b0, b1);
        }
    }

    const size_t grow = (size_t)i * 512 + j0;
#pragma unroll
    for (int mf = 0; mf < 2; mf++) {
#pragma unroll
        for (int nf = 0; nf < 4; nf++) {
            size_t row = grow + wm * 32 + mf * 16 + lr;
            int col = wn * 32 + nf * 8 + 2 * lc;
            float b0v = __ldg(ob + col), b1v = __ldg(ob + col + 1);
            float2 gt0 = *reinterpret_cast<const float2*>(g_gate + row * 128 + col);
            float2 gt1 = *reinterpret_cast<const float2*>(g_gate + (row + 8) * 128 + col);
            *reinterpret_cast<float2*>(out + row * 128 + col) =
                make_float2((acc[mf][nf][0] + b0v) * gt0.x, (acc[mf][nf][1] + b1v) * gt0.y);
            *reinterpret_cast<float2*>(out + (row + 8) * 128 + col) =
                make_float2((acc[mf][nf][2] + b0v) * gt1.x, (acc[mf][nf][3] + b1v) * gt1.y);
        }
    }
}

// ============================================================
// launch
// ============================================================
extern "C" void kernel_launch(void* const* d_in, const int* in_sizes, int n_in,
                              void* d_out, int out_size) {
    const float* z      = (const float*)d_in[0];
    const float* norm_g = (const float*)d_in[1];
    const float* norm_b = (const float*)d_in[2];
    const float* a_w    = (const float*)d_in[3];
    const float* a_b    = (const float*)d_in[4];
    const float* ag_w   = (const float*)d_in[5];
    const float* ag_b   = (const float*)d_in[6];
    const float* onorm_g= (const float*)d_in[7];
    const float* onorm_b= (const float*)d_in[8];
    const float* o_w    = (const float*)d_in[9];
    const float* o_b    = (const float*)d_in[10];
    const float* g_wp   = (const float*)d_in[11];
    const float* g_bp   = (const float*)d_in[12];
    float* out = (float*)d_out;

    static bool attr_done = false;
    if (!attr_done) {
        cudaFuncSetAttribute(fusedA,   cudaFuncAttributeMaxDynamicSharedMemorySize, 3 * 128 * 132 * 4);
        cudaFuncSetAttribute(syrk_mma, cudaFuncAttributeMaxDynamicSharedMemorySize, 2 * 9216 * 4);
        cudaFuncSetAttribute(fusedC,   cudaFuncAttributeMaxDynamicSharedMemorySize, 2 * 128 * 132 * 4);
        attr_done = true;
    }

    prep_w<<<128, 512>>>(a_w, ag_w, g_wp, o_w);
    fusedA<<<LL / 128, 512, 3 * 128 * 132 * 4>>>(z, norm_g, norm_b, a_b, ag_b, g_bp);
    syrk_mma<<<dim3(10, 128), 256, 2 * 9216 * 4>>>();
    fusedC<<<dim3(4, L), 512, 2 * 128 * 132 * 4>>>(onorm_g, onorm_b, o_b, out);
}